// round 1
// baseline (speedup 1.0000x reference)
#include <cuda_runtime.h>
#include <cstdint>

// ---------------- f32x2 + transcendental helpers ----------------

__device__ __forceinline__ unsigned long long pk2(float lo, float hi) {
    unsigned long long r;
    asm("mov.b64 %0, {%1, %2};" : "=l"(r) : "f"(lo), "f"(hi));
    return r;
}
__device__ __forceinline__ void up2(unsigned long long v, float& a, float& b) {
    asm("mov.b64 {%0, %1}, %2;" : "=f"(a), "=f"(b) : "l"(v));
}
__device__ __forceinline__ unsigned long long fma2(unsigned long long a,
                                                   unsigned long long b,
                                                   unsigned long long c) {
    unsigned long long d;
    asm("fma.rn.f32x2 %0, %1, %2, %3;" : "=l"(d) : "l"(a), "l"(b), "l"(c));
    return d;
}
__device__ __forceinline__ float tanha(float x) {
    float y;
    asm("tanh.approx.f32 %0, %1;" : "=f"(y) : "f"(x));
    return y;
}
__device__ __forceinline__ float sigm(float x) {
    return fmaf(0.5f, tanha(0.5f * x), 0.5f);
}

// ---------------- kernel ----------------
// B batch elems, T=4, I=2, H=16. One thread per batch element.
// Weights pre-packed into shared as (gate g, gate g+1) float2 pairs so the
// inner product runs on fma.rn.f32x2 (2 fp32 MACs / instr).

#define TT 4
#define HH 16

__global__ void __launch_bounds__(256)
gru_adder_kernel(const float* __restrict__ x,
                 const float* __restrict__ w_ih,   // [48,2]
                 const float* __restrict__ w_hh,   // [48,16]
                 const float* __restrict__ b_ih,   // [48]
                 const float* __restrict__ b_hh,   // [48]
                 const float* __restrict__ w_sum,  // [16]
                 const float* __restrict__ b_sum,  // [1]
                 const float* __restrict__ w_car,  // [16]
                 const float* __restrict__ b_car,  // [1]
                 float* __restrict__ out_hidden,   // [B,4,16]
                 float* __restrict__ out_sums,     // [B,4]
                 float* __restrict__ out_carry,    // [B,1]
                 float* __restrict__ out_ol,       // [B,5]
                 int Bn)
{
    // r,z gates: pairs p=0..7 -> rows (2p,2p+1) [r]; p=8..15 -> rows 16+2(p-8) [z]
    // entries k=0,1: w_ih; k=2..17: w_hh; k=18: b_ih+b_hh
    __shared__ unsigned long long s_rz[16][19];
    // n gate input part: rows 32..47. k=0,1: w_ih; k=2: b_ih
    __shared__ unsigned long long s_in[8][3];
    // n gate hidden part: k=0..15: w_hh; k=16: b_hh
    __shared__ unsigned long long s_hn[8][17];
    __shared__ float s_sumf[16], s_carf[16];
    __shared__ float s_bs, s_bc;

    const int tid = threadIdx.x;

    for (int idx = tid; idx < 16 * 19; idx += 256) {
        int p = idx / 19, k = idx % 19;
        int ga = (p < 8) ? 2 * p : 16 + 2 * (p - 8);
        int gb = ga + 1;
        unsigned long long v;
        if (k < 2)       v = pk2(w_ih[ga * 2 + k], w_ih[gb * 2 + k]);
        else if (k < 18) v = pk2(w_hh[ga * 16 + (k - 2)], w_hh[gb * 16 + (k - 2)]);
        else             v = pk2(b_ih[ga] + b_hh[ga], b_ih[gb] + b_hh[gb]);
        s_rz[p][k] = v;
    }
    for (int idx = tid; idx < 8 * 3; idx += 256) {
        int p = idx / 3, k = idx % 3;
        int ga = 32 + 2 * p, gb = ga + 1;
        s_in[p][k] = (k < 2) ? pk2(w_ih[ga * 2 + k], w_ih[gb * 2 + k])
                             : pk2(b_ih[ga], b_ih[gb]);
    }
    for (int idx = tid; idx < 8 * 17; idx += 256) {
        int p = idx / 17, k = idx % 17;
        int ga = 32 + 2 * p, gb = ga + 1;
        s_hn[p][k] = (k < 16) ? pk2(w_hh[ga * 16 + k], w_hh[gb * 16 + k])
                              : pk2(b_hh[ga], b_hh[gb]);
    }
    if (tid < 16)       s_sumf[tid] = w_sum[tid];
    else if (tid < 32)  s_carf[tid - 16] = w_car[tid - 16];
    else if (tid == 32) s_bs = b_sum[0];
    else if (tid == 33) s_bc = b_car[0];
    __syncthreads();

    const int b = blockIdx.x * 256 + tid;
    if (b >= Bn) return;

    // x: 8 contiguous floats per element -> 2 coalesced float4 loads
    const float4* xv = reinterpret_cast<const float4*>(x + (size_t)b * 8);
    float4 xa = xv[0], xbv = xv[1];
    float xs[8] = {xa.x, xa.y, xa.z, xa.w, xbv.x, xbv.y, xbv.z, xbv.w};

    float h[HH];
    unsigned long long hd[HH];   // (h[k], h[k]) duplicated packs
#pragma unroll
    for (int j = 0; j < HH; j++) { h[j] = 0.0f; hd[j] = 0ull; }

    float sums[TT];
    float4* oh = reinterpret_cast<float4*>(out_hidden + (size_t)b * (TT * HH));

#pragma unroll
    for (int t = 0; t < TT; t++) {
        const unsigned long long xd0 = pk2(xs[2 * t], xs[2 * t]);
        const unsigned long long xd1 = pk2(xs[2 * t + 1], xs[2 * t + 1]);

        float r[HH], z[HH];
#pragma unroll
        for (int p = 0; p < 16; p++) {
            unsigned long long acc = s_rz[p][18];
            acc = fma2(s_rz[p][0], xd0, acc);
            acc = fma2(s_rz[p][1], xd1, acc);
            if (t > 0) {   // h0 == 0: skip recurrent matmul at t=0
#pragma unroll
                for (int k = 0; k < HH; k++) acc = fma2(s_rz[p][2 + k], hd[k], acc);
            }
            float a0, a1;
            up2(acc, a0, a1);
            float v0 = sigm(a0), v1 = sigm(a1);
            if (p < 8) { r[2 * p] = v0; r[2 * p + 1] = v1; }
            else       { z[2 * p - 16] = v0; z[2 * p - 15] = v1; }
        }

        float nn[HH];
#pragma unroll
        for (int p = 0; p < 8; p++) {
            unsigned long long ia = s_in[p][2];
            ia = fma2(s_in[p][0], xd0, ia);
            ia = fma2(s_in[p][1], xd1, ia);
            unsigned long long ha = s_hn[p][16];
            if (t > 0) {
#pragma unroll
                for (int k = 0; k < HH; k++) ha = fma2(s_hn[p][k], hd[k], ha);
            }
            float i0, i1, g0, g1;
            up2(ia, i0, i1);
            up2(ha, g0, g1);
            nn[2 * p]     = tanha(fmaf(r[2 * p],     g0, i0));
            nn[2 * p + 1] = tanha(fmaf(r[2 * p + 1], g1, i1));
        }

        float s = s_bs;
#pragma unroll
        for (int j = 0; j < HH; j++) {
            // h' = (1-z)n + z h = n + z*(h-n)
            h[j]  = fmaf(z[j], h[j] - nn[j], nn[j]);
            hd[j] = pk2(h[j], h[j]);
            s     = fmaf(h[j], s_sumf[j], s);
        }
        sums[t] = s;

        oh[t * 4 + 0] = make_float4(h[0],  h[1],  h[2],  h[3]);
        oh[t * 4 + 1] = make_float4(h[4],  h[5],  h[6],  h[7]);
        oh[t * 4 + 2] = make_float4(h[8],  h[9],  h[10], h[11]);
        oh[t * 4 + 3] = make_float4(h[12], h[13], h[14], h[15]);
    }

    float c = s_bc;
#pragma unroll
    for (int j = 0; j < HH; j++) c = fmaf(h[j], s_carf[j], c);

    reinterpret_cast<float4*>(out_sums)[b] =
        make_float4(sums[0], sums[1], sums[2], sums[3]);
    out_carry[b] = c;

    float* ol = out_ol + (size_t)b * 5;
    ol[0] = sums[0];
    ol[1] = sums[1];
    ol[2] = sums[2];
    ol[3] = sums[3];
    ol[4] = c;
}

// ---------------- launch ----------------

extern "C" void kernel_launch(void* const* d_in, const int* in_sizes, int n_in,
                              void* d_out, int out_size)
{
    const float* x     = (const float*)d_in[0];
    const float* w_ih  = (const float*)d_in[1];
    const float* w_hh  = (const float*)d_in[2];
    const float* b_ih  = (const float*)d_in[3];
    const float* b_hh  = (const float*)d_in[4];
    const float* w_sum = (const float*)d_in[5];
    const float* b_sum = (const float*)d_in[6];
    const float* w_car = (const float*)d_in[7];
    const float* b_car = (const float*)d_in[8];

    const int B = in_sizes[0] / (TT * 2);   // x is [B, T=4, I=2]

    float* out = (float*)d_out;
    float* out_hidden = out;                                  // B*64
    float* out_sums   = out_hidden + (size_t)B * TT * HH;     // B*4
    float* out_carry  = out_sums + (size_t)B * TT;            // B
    float* out_ol     = out_carry + (size_t)B;                // B*5

    const int threads = 256;
    const int blocks = (B + threads - 1) / threads;
    gru_adder_kernel<<<blocks, threads>>>(x, w_ih, w_hh, b_ih, b_hh,
                                          w_sum, b_sum, w_car, b_car,
                                          out_hidden, out_sums, out_carry,
                                          out_ol, B);
}